// round 1
// baseline (speedup 1.0000x reference)
#include <cuda_runtime.h>
#include <stdint.h>

// ---------------- problem constants / scratch sizing ----------------
#define N_MAX   131072      // >= 100000 columns
#define E_MAX   1700000     // >= 1600000 edges
#define EPSF    1e-8f
#define GAMMA   0.1
// LAMBDA = 1.0

// ---------------- device scratch (static, no allocation) ----------------
__device__ float    d_colsum[N_MAX];
__device__ int      d_count[N_MAX];
__device__ int      d_offsets[N_MAX + 1];
__device__ int      d_cursor[N_MAX];
__device__ int      d_blocksums[1024];
__device__ int      d_blockoffs[1024];
__device__ float    d_snv[E_MAX];      // edge values sorted by column
__device__ int      d_srow[E_MAX];     // edge source rows sorted by column
__device__ unsigned d_hist[2][256];    // radix-select histograms
__device__ unsigned d_selprefix[2];
__device__ unsigned d_selkmask[2];
__device__ unsigned d_selk[2];
__device__ float    d_selres[2];
__device__ double   d_part[3][256];    // sliced partials: 0=reg, 1=recon, 2=block
__device__ int      d_row64, d_col64;  // index dtype flags

// ---------------- helpers ----------------
__device__ __forceinline__ int getIdx(const void* p, int e, int is64) {
    return is64 ? (int)((const long long*)p)[e] : ((const int*)p)[e];
}

__device__ __forceinline__ double blockReduceD(double v) {
    __shared__ double ws[32];
    __syncthreads();
    int lane = threadIdx.x & 31, w = threadIdx.x >> 5;
    #pragma unroll
    for (int o = 16; o; o >>= 1) v += __shfl_xor_sync(0xFFFFFFFFu, v, o);
    if (!lane) ws[w] = v;
    __syncthreads();
    int nw = (blockDim.x + 31) >> 5;
    v = (threadIdx.x < nw) ? ws[threadIdx.x] : 0.0;
    if (w == 0) {
        #pragma unroll
        for (int o = 16; o; o >>= 1) v += __shfl_xor_sync(0xFFFFFFFFu, v, o);
    }
    return v;  // valid on thread 0
}

// ---------------- kernels ----------------
__global__ void k_zero(int n, int E) {
    int i = blockIdx.x * blockDim.x + threadIdx.x;
    if (i < n) { d_colsum[i] = 0.f; d_count[i] = 0; }
    if (i < 512) d_hist[i >> 8][i & 255] = 0u;
    if (i < 768) d_part[i >> 8][i & 255] = 0.0;
    if (i < 2) {
        d_selprefix[i] = 0u;
        d_selkmask[i]  = 0u;
        d_selk[i]      = (unsigned)(E / 2 - 1 + i);  // two middle order stats
    }
}

// Detect int64 vs int32 index arrays: for int64 (values < 2^31), every odd
// 32-bit word is a zero high half. Sample 512 odd words (all < E, safe for both).
__global__ void k_detect(const void* rowp, const void* colp, int E) {
    __shared__ int nzr, nzc;
    if (threadIdx.x == 0) { nzr = 0; nzc = 0; }
    __syncthreads();
    const unsigned* r = (const unsigned*)rowp;
    const unsigned* c = (const unsigned*)colp;
    for (int s = threadIdx.x; s < 512; s += blockDim.x) {
        int i = 2 * s + 1;  // odd indices 1..1023, < E for both dtypes
        if (r[i]) atomicOr(&nzr, 1);
        if (c[i]) atomicOr(&nzc, 1);
    }
    __syncthreads();
    if (threadIdx.x == 0) { d_row64 = nzr ? 0 : 1; d_col64 = nzc ? 0 : 1; }
}

__global__ void k_count(const float* __restrict__ C, const void* __restrict__ colp, int E) {
    int e = blockIdx.x * blockDim.x + threadIdx.x;
    if (e >= E) return;
    int is64 = d_col64;
    int c = getIdx(colp, e, is64);
    atomicAdd(&d_count[c], 1);
    atomicAdd(&d_colsum[c], C[e]);
}

__global__ void k_scan1(int n) {
    __shared__ int s[1024];
    int t = threadIdx.x, i = blockIdx.x * 1024 + t;
    int x = (i < n) ? d_count[i] : 0;
    s[t] = x; __syncthreads();
    #pragma unroll
    for (int off = 1; off < 1024; off <<= 1) {
        int v = (t >= off) ? s[t - off] : 0;
        __syncthreads();
        s[t] += v;
        __syncthreads();
    }
    if (i < n) d_offsets[i] = s[t] - x;      // exclusive within block
    if (t == 1023) d_blocksums[blockIdx.x] = s[1023];
}

__global__ void k_scan2(int B) {
    __shared__ int s[1024];
    int t = threadIdx.x;
    int x = (t < B) ? d_blocksums[t] : 0;
    s[t] = x; __syncthreads();
    #pragma unroll
    for (int off = 1; off < 1024; off <<= 1) {
        int v = (t >= off) ? s[t - off] : 0;
        __syncthreads();
        s[t] += v;
        __syncthreads();
    }
    if (t < B) d_blockoffs[t] = s[t] - x;    // exclusive block offsets
}

__global__ void k_scan3(int n, int E) {
    int i = blockIdx.x * blockDim.x + threadIdx.x;
    if (i < n) {
        int o = d_offsets[i] + d_blockoffs[i >> 10];
        d_offsets[i] = o;
        d_cursor[i]  = o;
    }
    if (i == 0) d_offsets[n] = E;
}

// norm_vals + regularization sum + scatter edge payloads into column bins
__global__ void k_norm(const float* __restrict__ C, const void* __restrict__ rowp,
                       const void* __restrict__ colp, float* __restrict__ out, int E) {
    int e = blockIdx.x * blockDim.x + threadIdx.x;
    int r64 = d_row64, c64 = d_col64;
    float nv = 0.f;
    if (e < E) {
        int c = getIdx(colp, e, c64);
        int r = getIdx(rowp, e, r64);
        nv = C[e] / (d_colsum[c] + EPSF);
        out[e] = nv;
        int pos = atomicAdd(&d_cursor[c], 1);
        d_snv[pos]  = nv;
        d_srow[pos] = r;
    }
    double v = blockReduceD((double)nv * (double)nv);
    if (threadIdx.x == 0) atomicAdd(&d_part[0][blockIdx.x & 255], v);
}

// One warp per column: accumulate C^T Z row in registers (4 x float4 per lane),
// fuse the (Z_recon - Z)^2 reduction. Z stays L2-resident.
__global__ void k_recon(const float4* __restrict__ Z4, int n) {
    int warp = (blockIdx.x * blockDim.x + threadIdx.x) >> 5;
    int lane = threadIdx.x & 31;
    float ssq = 0.f;
    if (warp < n) {
        int s = d_offsets[warp], e = d_offsets[warp + 1];
        float4 acc = make_float4(0.f, 0.f, 0.f, 0.f);
        for (int i = s; i < e; i++) {
            float nv = d_snv[i];
            int   r  = d_srow[i];
            float4 z = Z4[(long)r * 32 + lane];
            acc.x = fmaf(nv, z.x, acc.x);
            acc.y = fmaf(nv, z.y, acc.y);
            acc.z = fmaf(nv, z.z, acc.z);
            acc.w = fmaf(nv, z.w, acc.w);
        }
        float4 zj = Z4[(long)warp * 32 + lane];
        float dx = acc.x - zj.x, dy = acc.y - zj.y, dz = acc.z - zj.z, dw = acc.w - zj.w;
        ssq = dx * dx + dy * dy + dz * dz + dw * dw;
    }
    double v = blockReduceD((double)ssq);
    if (threadIdx.x == 0) atomicAdd(&d_part[1][blockIdx.x & 255], v);
}

// Radix-select histogram pass over |norm_vals| bit patterns
__global__ void k_selhist(const float* __restrict__ out, int E, int which, int shift) {
    __shared__ unsigned sh[256];
    for (int i = threadIdx.x; i < 256; i += blockDim.x) sh[i] = 0u;
    __syncthreads();
    unsigned pref = d_selprefix[which], kmask = d_selkmask[which];
    for (int e = blockIdx.x * blockDim.x + threadIdx.x; e < E; e += gridDim.x * blockDim.x) {
        unsigned b = __float_as_uint(out[e]) & 0x7FFFFFFFu;
        if ((b & kmask) == pref) atomicAdd(&sh[(b >> shift) & 0xFF], 1u);
    }
    __syncthreads();
    for (int i = threadIdx.x; i < 256; i += blockDim.x)
        if (sh[i]) atomicAdd(&d_hist[which][i], sh[i]);
}

__global__ void k_selstep(int which, int shift) {
    unsigned cum = 0, k = d_selk[which];
    #pragma unroll 1
    for (int v = 0; v < 256; v++) {
        unsigned c = d_hist[which][v];
        if (k < cum + c) {
            d_selprefix[which] |= ((unsigned)v << shift);
            d_selk[which] = k - cum;
            break;
        }
        cum += c;
    }
    d_selkmask[which] |= (0xFFu << shift);
    for (int v = 0; v < 256; v++) d_hist[which][v] = 0u;
    if (shift == 0) d_selres[which] = __uint_as_float(d_selprefix[which]);
}

__global__ void k_block(const float* __restrict__ out, int E) {
    float thr = 0.5f * (d_selres[0] + d_selres[1]);
    double local = 0.0;
    for (int e = blockIdx.x * blockDim.x + threadIdx.x; e < E; e += gridDim.x * blockDim.x) {
        float nv = out[e];
        if (fabsf(nv) < thr) local += (double)nv * (double)nv;
    }
    double v = blockReduceD(local);
    if (threadIdx.x == 0) atomicAdd(&d_part[2][blockIdx.x & 255], v);
}

__global__ void k_fin(float* __restrict__ out, int base, int n) {
    int t = threadIdx.x;  // 256 threads
    double reg = d_part[0][t];
    double rec = d_part[1][t];
    double blk = d_part[2][t];
    reg = blockReduceD(reg);
    rec = blockReduceD(rec);
    blk = blockReduceD(blk);
    if (t == 0) {
        out[base + 0] = (float)(rec / ((double)n * 128.0));  // recon_loss (mean)
        out[base + 1] = (float)reg;                          // reg_loss (LAMBDA=1)
        out[base + 2] = (float)(GAMMA * blk);                // block_loss
    }
}

// ---------------- launch ----------------
extern "C" void kernel_launch(void* const* d_in, const int* in_sizes, int n_in,
                              void* d_out, int out_size) {
    const float* Z    = (const float*)d_in[0];
    const float* C    = (const float*)d_in[1];
    const void*  rowp = d_in[2];
    const void*  colp = d_in[3];
    float* out = (float*)d_out;

    int n = in_sizes[0] / 128;   // N_SAMPLES
    int E = in_sizes[1];         // NUM_EDGES

    const int TB = 256;
    int gE = (E + TB - 1) / TB;
    int gN = (n + TB - 1) / TB;
    int B  = (n + 1023) / 1024;

    k_zero<<<gN, TB>>>(n, E);
    k_detect<<<1, 256>>>(rowp, colp, E);
    k_count<<<gE, TB>>>(C, colp, E);
    k_scan1<<<B, 1024>>>(n);
    k_scan2<<<1, 1024>>>(B);
    k_scan3<<<gN, TB>>>(n, E);
    k_norm<<<gE, TB>>>(C, rowp, colp, out, E);
    k_recon<<<(n + 7) / 8, 256>>>((const float4*)Z, n);
    for (int w = 0; w < 2; w++) {
        for (int p = 0; p < 4; p++) {
            k_selhist<<<512, 256>>>(out, E, w, 24 - 8 * p);
            k_selstep<<<1, 1>>>(w, 24 - 8 * p);
        }
    }
    k_block<<<512, 256>>>(out, E);
    k_fin<<<1, 256>>>(out, out_size - 3, n);
}